// round 5
// baseline (speedup 1.0000x reference)
#include <cuda_runtime.h>
#include <math.h>

#define BATCH   128
#define TSTEPS  256
#define HORIZON 512
#define OBS     32
#define LAT     256
#define HID     1024
#define NB2     296              // 2 CTAs/SM x 148 SMs, all co-resident
#define ZSTRIDE (BATCH * LAT)

// ---------------------------------------------------------------------------
// Scratch
// ---------------------------------------------------------------------------
__device__ float g_Z[(size_t)(HORIZON + 1) * ZSTRIDE];
__device__ float g_A[(size_t)128 * BATCH * HID];   // phase1b acts / phase2 partials
__device__ float g_B[(size_t)128 * BATCH * HID];
__device__ float g_C[BATCH * LAT];
__device__ unsigned g_bar;

// ---------------------------------------------------------------------------
// f32x2 helpers
// ---------------------------------------------------------------------------
typedef unsigned long long u64;
__device__ __forceinline__ u64 f2dup(float s) {
    u64 r; asm("mov.b64 %0, {%1, %1};" : "=l"(r) : "f"(s)); return r;
}
__device__ __forceinline__ void f2fma(u64& d, u64 a, u64 b) {
    asm("fma.rn.f32x2 %0, %1, %2, %0;" : "+l"(d) : "l"(a), "l"(b));
}
__device__ __forceinline__ float2 f2unpack(u64 v) {
    float2 r; asm("mov.b64 {%0, %1}, %2;" : "=f"(r.x), "=f"(r.y) : "l"(v)); return r;
}

// ---------------------------------------------------------------------------
// Grid barrier
// ---------------------------------------------------------------------------
__device__ __forceinline__ void gsync(unsigned& target) {
    target += gridDim.x;
    __syncthreads();
    if (threadIdx.x == 0) {
        __threadfence();
        atomicAdd(&g_bar, 1u);
        while (*((volatile unsigned*)&g_bar) < target) {}
        __threadfence();
    }
    __syncthreads();
}

// ---------------------------------------------------------------------------
// Phase 1a: barrier-free recurrence. CTA b owns batch row b.
// ---------------------------------------------------------------------------
__global__ void __launch_bounds__(256) phase1a_kernel(
    const float* __restrict__ y,
    const float* __restrict__ Wih, const float* __restrict__ Whh,
    const float* __restrict__ bih, const float* __restrict__ bhh,
    float* __restrict__ Z)
{
    const int b = blockIdx.x, tid = threadIdx.x;
    __shared__ float sz[LAT];
    __shared__ float sy[OBS];

    sz[tid] = 0.0f;
    __stcg(Z + (size_t)b * LAT + tid, 0.0f);
    float bsum = __ldg(bih + tid) + __ldg(bhh + tid);

    float4 wi[8];
    const float4* wip = (const float4*)(Wih + (size_t)tid * OBS);
#pragma unroll
    for (int k = 0; k < 8; k++) wi[k] = __ldg(wip + k);
    const float4* wh = (const float4*)(Whh + (size_t)tid * LAT);
    __syncthreads();

    for (int t = 0; t < TSTEPS; t++) {
        if (tid < OBS) sy[tid] = __ldg(y + ((size_t)b * TSTEPS + t) * OBS + tid);
        __syncthreads();
        float acc = bsum;
#pragma unroll
        for (int k = 0; k < 8; k++) {
            float4 w = wi[k];
            acc += sy[k*4+0]*w.x + sy[k*4+1]*w.y + sy[k*4+2]*w.z + sy[k*4+3]*w.w;
        }
#pragma unroll 8
        for (int k = 0; k < 64; k++) {
            float4 w = __ldg(wh + k);
            acc += sz[k*4+0]*w.x + sz[k*4+1]*w.y + sz[k*4+2]*w.z + sz[k*4+3]*w.w;
        }
        float zn = tanhf(acc);
        __syncthreads();
        sz[tid] = zn;
        __stcg(Z + ((size_t)t + 1) * ZSTRIDE + (size_t)b * LAT + tid, zn);
    }
}

// ---------------------------------------------------------------------------
// Phase 1b GEMM (unchanged from round 4): 128x128 tile, 8x8 microtile.
// ---------------------------------------------------------------------------
template<int ACT>
__global__ void __launch_bounds__(256, 2) gemm_big(
    const float* __restrict__ X, int ldx,
    const float* __restrict__ W, int ldw,
    const float* __restrict__ bias,
    float* __restrict__ Y, int ldy, int K)
{
    __shared__ __align__(16) float sX[16 * 132];
    __shared__ __align__(16) float sW[16 * 132];
    const int tid = threadIdx.x;
    const int ty = tid >> 4, tx = tid & 15;
    const int mB = blockIdx.y * 128, nB = blockIdx.x * 128;
    const int xr = tid >> 2, xc = tid & 3;

    const float* Xp0 = X + (size_t)(mB + xr) * ldx + xc * 4;
    const float* Xp1 = Xp0 + (size_t)64 * ldx;
    const float* Wp0 = W + (size_t)(nB + xr) * ldw + xc * 4;
    const float* Wp1 = Wp0 + (size_t)64 * ldw;

    float4 xv0 = __ldg((const float4*)Xp0);
    float4 xv1 = __ldg((const float4*)Xp1);
    float4 wv0 = __ldg((const float4*)Wp0);
    float4 wv1 = __ldg((const float4*)Wp1);

    u64 acc[4][8];
#pragma unroll
    for (int i = 0; i < 4; i++)
#pragma unroll
        for (int j = 0; j < 8; j++) acc[i][j] = 0ull;

    for (int k0 = 0;;) {
        sX[(xc*4+0)*132 + xr] = xv0.x; sX[(xc*4+1)*132 + xr] = xv0.y;
        sX[(xc*4+2)*132 + xr] = xv0.z; sX[(xc*4+3)*132 + xr] = xv0.w;
        sX[(xc*4+0)*132 + xr+64] = xv1.x; sX[(xc*4+1)*132 + xr+64] = xv1.y;
        sX[(xc*4+2)*132 + xr+64] = xv1.z; sX[(xc*4+3)*132 + xr+64] = xv1.w;
        sW[(xc*4+0)*132 + xr] = wv0.x; sW[(xc*4+1)*132 + xr] = wv0.y;
        sW[(xc*4+2)*132 + xr] = wv0.z; sW[(xc*4+3)*132 + xr] = wv0.w;
        sW[(xc*4+0)*132 + xr+64] = wv1.x; sW[(xc*4+1)*132 + xr+64] = wv1.y;
        sW[(xc*4+2)*132 + xr+64] = wv1.z; sW[(xc*4+3)*132 + xr+64] = wv1.w;
        __syncthreads();

        const int k1 = k0 + 16;
        if (k1 < K) {
            xv0 = __ldg((const float4*)(Xp0 + k1));
            xv1 = __ldg((const float4*)(Xp1 + k1));
            wv0 = __ldg((const float4*)(Wp0 + k1));
            wv1 = __ldg((const float4*)(Wp1 + k1));
        }
#pragma unroll
        for (int kk = 0; kk < 16; kk++) {
            ulonglong2 aA = *(const ulonglong2*)&sX[kk*132 + ty*8];
            ulonglong2 aB = *(const ulonglong2*)&sX[kk*132 + ty*8 + 4];
            float4 b0 = *(const float4*)&sW[kk*132 + tx*8];
            float4 b1 = *(const float4*)&sW[kk*132 + tx*8 + 4];
            u64 bd[8];
            bd[0]=f2dup(b0.x); bd[1]=f2dup(b0.y); bd[2]=f2dup(b0.z); bd[3]=f2dup(b0.w);
            bd[4]=f2dup(b1.x); bd[5]=f2dup(b1.y); bd[6]=f2dup(b1.z); bd[7]=f2dup(b1.w);
#pragma unroll
            for (int j = 0; j < 8; j++) {
                f2fma(acc[0][j], aA.x, bd[j]);
                f2fma(acc[1][j], aA.y, bd[j]);
                f2fma(acc[2][j], aB.x, bd[j]);
                f2fma(acc[3][j], aB.y, bd[j]);
            }
        }
        __syncthreads();
        if (k1 >= K) break;
        k0 = k1;
    }

    float4 bb0 = __ldg((const float4*)(bias + nB + tx * 8));
    float4 bb1 = __ldg((const float4*)(bias + nB + tx * 8 + 4));
#pragma unroll
    for (int mp = 0; mp < 4; mp++) {
        float2 u[8];
#pragma unroll
        for (int j = 0; j < 8; j++) u[j] = f2unpack(acc[mp][j]);
        float4 r0a = make_float4(u[0].x+bb0.x, u[1].x+bb0.y, u[2].x+bb0.z, u[3].x+bb0.w);
        float4 r0b = make_float4(u[4].x+bb1.x, u[5].x+bb1.y, u[6].x+bb1.z, u[7].x+bb1.w);
        float4 r1a = make_float4(u[0].y+bb0.x, u[1].y+bb0.y, u[2].y+bb0.z, u[3].y+bb0.w);
        float4 r1b = make_float4(u[4].y+bb1.x, u[5].y+bb1.y, u[6].y+bb1.z, u[7].y+bb1.w);
        if (ACT) {
            r0a.x=fmaxf(r0a.x,0.f); r0a.y=fmaxf(r0a.y,0.f); r0a.z=fmaxf(r0a.z,0.f); r0a.w=fmaxf(r0a.w,0.f);
            r0b.x=fmaxf(r0b.x,0.f); r0b.y=fmaxf(r0b.y,0.f); r0b.z=fmaxf(r0b.z,0.f); r0b.w=fmaxf(r0b.w,0.f);
            r1a.x=fmaxf(r1a.x,0.f); r1a.y=fmaxf(r1a.y,0.f); r1a.z=fmaxf(r1a.z,0.f); r1a.w=fmaxf(r1a.w,0.f);
            r1b.x=fmaxf(r1b.x,0.f); r1b.y=fmaxf(r1b.y,0.f); r1b.z=fmaxf(r1b.z,0.f); r1b.w=fmaxf(r1b.w,0.f);
        }
        const int row0 = mB + ty * 8 + mp * 2;
        float* y0 = Y + (size_t)row0 * ldy + nB + tx * 8;
        float* y1 = y0 + ldy;
        *(float4*)y0 = r0a; *(float4*)(y0 + 4) = r0b;
        *(float4*)y1 = r1a; *(float4*)(y1 + 4) = r1b;
    }
}

// ---------------------------------------------------------------------------
// Phase 1b output layer (unchanged).
// ---------------------------------------------------------------------------
__global__ void __launch_bounds__(256) gemm_out(
    const float* __restrict__ X, int ldx,
    const float* __restrict__ W, int ldw,
    const float* __restrict__ bias,
    float* __restrict__ out, int K, int t0)
{
    __shared__ __align__(16) float sX[16 * 132];
    __shared__ __align__(16) float sW[16 * 36];
    const int tid = threadIdx.x;
    const int ty = tid >> 4, tx = tid & 15;
    const int mB = blockIdx.y * 128;
    const int xr = tid >> 2, xc = tid & 3;

    const float* Xp0 = X + (size_t)(mB + xr) * ldx + xc * 4;
    const float* Xp1 = Xp0 + (size_t)64 * ldx;
    const bool wp = tid < 128;
    const float* Wp = W + (size_t)xr * ldw + xc * 4;

    float4 xv0 = __ldg((const float4*)Xp0);
    float4 xv1 = __ldg((const float4*)Xp1);
    float4 wv = make_float4(0,0,0,0);
    if (wp) wv = __ldg((const float4*)Wp);

    float acc[8][2];
#pragma unroll
    for (int i = 0; i < 8; i++) { acc[i][0] = 0.f; acc[i][1] = 0.f; }

    for (int k0 = 0;;) {
        sX[(xc*4+0)*132 + xr] = xv0.x; sX[(xc*4+1)*132 + xr] = xv0.y;
        sX[(xc*4+2)*132 + xr] = xv0.z; sX[(xc*4+3)*132 + xr] = xv0.w;
        sX[(xc*4+0)*132 + xr+64] = xv1.x; sX[(xc*4+1)*132 + xr+64] = xv1.y;
        sX[(xc*4+2)*132 + xr+64] = xv1.z; sX[(xc*4+3)*132 + xr+64] = xv1.w;
        if (wp) {
            sW[(xc*4+0)*36 + xr] = wv.x; sW[(xc*4+1)*36 + xr] = wv.y;
            sW[(xc*4+2)*36 + xr] = wv.z; sW[(xc*4+3)*36 + xr] = wv.w;
        }
        __syncthreads();
        const int k1 = k0 + 16;
        if (k1 < K) {
            xv0 = __ldg((const float4*)(Xp0 + k1));
            xv1 = __ldg((const float4*)(Xp1 + k1));
            if (wp) wv = __ldg((const float4*)(Wp + k1));
        }
#pragma unroll
        for (int kk = 0; kk < 16; kk++) {
            float4 a0 = *(const float4*)&sX[kk*132 + ty*8];
            float4 a1 = *(const float4*)&sX[kk*132 + ty*8 + 4];
            float2 b  = *(const float2*)&sW[kk*36 + tx*2];
            acc[0][0]+=a0.x*b.x; acc[0][1]+=a0.x*b.y;
            acc[1][0]+=a0.y*b.x; acc[1][1]+=a0.y*b.y;
            acc[2][0]+=a0.z*b.x; acc[2][1]+=a0.z*b.y;
            acc[3][0]+=a0.w*b.x; acc[3][1]+=a0.w*b.y;
            acc[4][0]+=a1.x*b.x; acc[4][1]+=a1.x*b.y;
            acc[5][0]+=a1.y*b.x; acc[5][1]+=a1.y*b.y;
            acc[6][0]+=a1.z*b.x; acc[6][1]+=a1.z*b.y;
            acc[7][0]+=a1.w*b.x; acc[7][1]+=a1.w*b.y;
        }
        __syncthreads();
        if (k1 >= K) break;
        k0 = k1;
    }

    float2 bb = *(const float2*)(bias + tx * 2);
#pragma unroll
    for (int i = 0; i < 8; i++) {
        int r = mB + ty * 8 + i;
        int b = r & (BATCH - 1);
        int t = t0 + (r >> 7);
        float2 v = make_float2(acc[i][0] + bb.x, acc[i][1] + bb.y);
        *(float2*)(out + ((size_t)b * HORIZON + t) * OBS + tx * 2) = v;
    }
}

// ---------------------------------------------------------------------------
// Phase-2 split-K tile: 16x64, 128 thr. Computes a RAW partial over
// K range [kOff, kOff+Keff) and stores it (no bias/relu).
// COMBINE: X element = relu(X0 + X1 + bIn) fused at load time.
// ---------------------------------------------------------------------------
template<bool COMBINE>
__device__ __forceinline__ void tile16x64(
    int mB, int nB, int kOff, int Keff,
    const float* __restrict__ X0, const float* __restrict__ X1,
    const float* __restrict__ bIn, int ldx,
    const float* __restrict__ W, int ldw,
    float* __restrict__ Pout, int ldp,
    float* sX, float* sW)
{
    const int tid = threadIdx.x;
    const int ty = tid >> 4, tx = tid & 15;
    const int xr = tid >> 3, xc = tid & 7;

    const float* Xp = X0 + (size_t)(mB + xr) * ldx + kOff + xc * 4;
    const float* Xq = X1 + (size_t)(mB + xr) * ldx + kOff + xc * 4;  // unused if !COMBINE
    const float* Bp = bIn + kOff + xc * 4;
    const float* Wp = W + (size_t)(nB + xr) * ldw + kOff + xc * 4;

    float4 xv;
    {
        float4 a = __ldcg((const float4*)Xp);
        if constexpr (COMBINE) {
            float4 b = __ldcg((const float4*)Xq);
            float4 c = __ldg((const float4*)Bp);
            xv = make_float4(fmaxf(a.x+b.x+c.x, 0.f), fmaxf(a.y+b.y+c.y, 0.f),
                             fmaxf(a.z+b.z+c.z, 0.f), fmaxf(a.w+b.w+c.w, 0.f));
        } else xv = a;
    }
    float4 wv[4];
#pragma unroll
    for (int j = 0; j < 4; j++)
        wv[j] = __ldg((const float4*)(Wp + (size_t)(j * 16) * ldw));

    u64 acc[2][2] = {{0ull,0ull},{0ull,0ull}};

    for (int k0 = 0;;) {
        sX[(xc*4+0)*17 + xr] = xv.x; sX[(xc*4+1)*17 + xr] = xv.y;
        sX[(xc*4+2)*17 + xr] = xv.z; sX[(xc*4+3)*17 + xr] = xv.w;
#pragma unroll
        for (int j = 0; j < 4; j++) {
            int wr = xr + j * 16;
            sW[(xc*4+0)*68 + wr] = wv[j].x; sW[(xc*4+1)*68 + wr] = wv[j].y;
            sW[(xc*4+2)*68 + wr] = wv[j].z; sW[(xc*4+3)*68 + wr] = wv[j].w;
        }
        __syncthreads();
        const int k1 = k0 + 32;
        if (k1 < Keff) {
            float4 a = __ldcg((const float4*)(Xp + k1));
            if constexpr (COMBINE) {
                float4 b = __ldcg((const float4*)(Xq + k1));
                float4 c = __ldg((const float4*)(Bp + k1));
                xv = make_float4(fmaxf(a.x+b.x+c.x, 0.f), fmaxf(a.y+b.y+c.y, 0.f),
                                 fmaxf(a.z+b.z+c.z, 0.f), fmaxf(a.w+b.w+c.w, 0.f));
            } else xv = a;
#pragma unroll
            for (int j = 0; j < 4; j++)
                wv[j] = __ldg((const float4*)(Wp + (size_t)(j * 16) * ldw + k1));
        }
#pragma unroll
        for (int kk = 0; kk < 32; kk++) {
            u64 a0 = f2dup(sX[kk*17 + ty]);
            u64 a1 = f2dup(sX[kk*17 + ty + 8]);
            ulonglong2 bp = *(const ulonglong2*)&sW[kk*68 + tx*4];
            f2fma(acc[0][0], a0, bp.x); f2fma(acc[0][1], a0, bp.y);
            f2fma(acc[1][0], a1, bp.x); f2fma(acc[1][1], a1, bp.y);
        }
        __syncthreads();
        if (k1 >= Keff) break;
        k0 = k1;
    }

#pragma unroll
    for (int i = 0; i < 2; i++) {
        int row = mB + ty + i * 8;
        float2 p0 = f2unpack(acc[i][0]);
        float2 p1 = f2unpack(acc[i][1]);
        float4 v = make_float4(p0.x, p0.y, p1.x, p1.y);
        __stcg((float4*)(Pout + (size_t)row * ldp + nB + tx * 4), v);
    }
}

// ---------------------------------------------------------------------------
// Phase 2: persistent AR rollout, 296 CTAs (2/SM), 5 barriers/step.
//   Regions 1-4: layer GEMM split-K over 256 CTAs + 8 Whh tiles on 256..263
//   Region 5: per-batch-row fused combine(L4) + L5 + out write + cell finish
// ---------------------------------------------------------------------------
__global__ void __launch_bounds__(128) phase2_kernel(
    const float* __restrict__ W1, const float* __restrict__ b1,
    const float* __restrict__ W2, const float* __restrict__ b2,
    const float* __restrict__ W3, const float* __restrict__ b3,
    const float* __restrict__ W4, const float* __restrict__ b4,
    const float* __restrict__ W5, const float* __restrict__ b5,
    const float* __restrict__ Wih, const float* __restrict__ Whh,
    const float* __restrict__ bih, const float* __restrict__ bhh,
    float* __restrict__ Z, float* __restrict__ P,
    float* __restrict__ C, float* __restrict__ out)
{
    __shared__ __align__(16) float sX[32 * 17];
    __shared__ __align__(16) float sW[32 * 68];
    unsigned target = 0;
    const int bid = blockIdx.x;
    const int tid = threadIdx.x;

    // partial buffers carved out of P (each 128 x 1024)
    float* PA0 = P;
    float* PA1 = P + 131072;
    float* PB0 = P + 262144;
    float* PB1 = P + 393216;

    const int ksel = bid & 1;
    const int tile = bid >> 1;                  // 0..127 for bid<256
    const int mT = (tile >> 4) * 16;
    const int nT = (tile & 15) * 64;

    for (int t = TSTEPS; t < HORIZON; t++) {
        const float* z = Z + (size_t)t * ZSTRIDE;

        // R1: L1 (K=256, split 128) -> PA ; Whh tiles 0..7
        if (bid < 256) {
            tile16x64<false>(mT, nT, ksel * 128, 128, z, z, b1, LAT,
                             W1, LAT, ksel ? PA1 : PA0, HID, sX, sW);
        } else if (bid < 264) {
            int wt = bid - 256;
            tile16x64<false>((wt >> 2) * 16, (wt & 3) * 64, 0, LAT, z, z, b1, LAT,
                             Whh, LAT, C, LAT, sX, sW);
        }
        gsync(target);

        // R2: L2 = relu(PA0+PA1+b1) @ W2 (K=1024, split 512) -> PB ; Whh 8..15
        if (bid < 256) {
            tile16x64<true>(mT, nT, ksel * 512, 512, PA0, PA1, b1, HID,
                            W2, HID, ksel ? PB1 : PB0, HID, sX, sW);
        } else if (bid < 264) {
            int wt = 8 + (bid - 256);
            tile16x64<false>((wt >> 2) * 16, (wt & 3) * 64, 0, LAT, z, z, b1, LAT,
                             Whh, LAT, C, LAT, sX, sW);
        }
        gsync(target);

        // R3: L3 -> PA ; Whh 16..23
        if (bid < 256) {
            tile16x64<true>(mT, nT, ksel * 512, 512, PB0, PB1, b2, HID,
                            W3, HID, ksel ? PA1 : PA0, HID, sX, sW);
        } else if (bid < 264) {
            int wt = 16 + (bid - 256);
            tile16x64<false>((wt >> 2) * 16, (wt & 3) * 64, 0, LAT, z, z, b1, LAT,
                             Whh, LAT, C, LAT, sX, sW);
        }
        gsync(target);

        // R4: L4 -> PB ; Whh 24..31
        if (bid < 256) {
            tile16x64<true>(mT, nT, ksel * 512, 512, PA0, PA1, b3, HID,
                            W4, HID, ksel ? PB1 : PB0, HID, sX, sW);
        } else if (bid < 264) {
            int wt = 24 + (bid - 256);
            tile16x64<false>((wt >> 2) * 16, (wt & 3) * 64, 0, LAT, z, z, b1, LAT,
                             Whh, LAT, C, LAT, sX, sW);
        }
        gsync(target);

        // R5: CTA b: h4 = relu(PB0+PB1+b4); yh = h4 @ W5^T + b5; write out;
        //     z_{t+1} = tanh(C + yh @ Wih^T + bih + bhh)
        if (bid < 128) {
            const int b = bid;
            const float4* r0 = (const float4*)(PB0 + (size_t)b * HID);
            const float4* r1 = (const float4*)(PB1 + (size_t)b * HID);
            const float4* bb4 = (const float4*)b4;
            for (int i = tid; i < 256; i += 128) {
                float4 q0 = __ldcg(r0 + i);
                float4 q1 = __ldcg(r1 + i);
                float4 c4 = __ldg(bb4 + i);
                float4 v = make_float4(fmaxf(q0.x+q1.x+c4.x, 0.f),
                                       fmaxf(q0.y+q1.y+c4.y, 0.f),
                                       fmaxf(q0.z+q1.z+c4.z, 0.f),
                                       fmaxf(q0.w+q1.w+c4.w, 0.f));
                ((float4*)sW)[i] = v;
            }
            __syncthreads();
            {
                const int n = tid >> 2, q = tid & 3;
                const float4* w5 = (const float4*)(W5 + (size_t)n * HID) + q * 64;
                const float4* xb = (const float4*)sW + q * 64;
                float s = 0.f;
#pragma unroll 8
                for (int k = 0; k < 64; k++) {
                    float4 w = __ldg(w5 + k);
                    float4 x = xb[k];
                    s += x.x*w.x + x.y*w.y + x.z*w.z + x.w*w.w;
                }
                sX[tid] = s;
            }
            __syncthreads();
            if (tid < OBS) {
                float yh = sX[tid*4] + sX[tid*4+1] + sX[tid*4+2] + sX[tid*4+3]
                         + __ldg(b5 + tid);
                __stcg(out + ((size_t)b * HORIZON + t) * OBS + tid, yh);
                sX[256 + tid] = yh;
            }
            __syncthreads();
            if (t < HORIZON - 1) {
#pragma unroll
                for (int p = 0; p < 2; p++) {
                    const int n = tid + p * 128;
                    float acc = __ldcg(C + (size_t)b * LAT + n)
                              + __ldg(bih + n) + __ldg(bhh + n);
                    const float4* wr = (const float4*)(Wih + (size_t)n * OBS);
#pragma unroll
                    for (int k = 0; k < 8; k++) {
                        float4 w = __ldg(wr + k);
                        acc += sX[256+k*4+0]*w.x + sX[256+k*4+1]*w.y
                             + sX[256+k*4+2]*w.z + sX[256+k*4+3]*w.w;
                    }
                    __stcg(Z + ((size_t)t + 1) * ZSTRIDE + (size_t)b * LAT + n, tanhf(acc));
                }
            }
        }
        gsync(target);
    }
}

// ---------------------------------------------------------------------------
// Launch (13 graph nodes)
// ---------------------------------------------------------------------------
extern "C" void kernel_launch(void* const* d_in, const int* in_sizes, int n_in,
                              void* d_out, int out_size)
{
    const float* y   = (const float*)d_in[0];
    const float* Wih = (const float*)d_in[2];
    const float* Whh = (const float*)d_in[3];
    const float* bih = (const float*)d_in[4];
    const float* bhh = (const float*)d_in[5];
    const float* W1  = (const float*)d_in[6];
    const float* b1  = (const float*)d_in[7];
    const float* W2  = (const float*)d_in[8];
    const float* b2  = (const float*)d_in[9];
    const float* W3  = (const float*)d_in[10];
    const float* b3  = (const float*)d_in[11];
    const float* W4  = (const float*)d_in[12];
    const float* b4  = (const float*)d_in[13];
    const float* W5  = (const float*)d_in[14];
    const float* b5  = (const float*)d_in[15];
    float* out = (float*)d_out;

    float *Z, *A, *Bf, *C;
    unsigned* bar;
    cudaGetSymbolAddress((void**)&Z,   g_Z);
    cudaGetSymbolAddress((void**)&A,   g_A);
    cudaGetSymbolAddress((void**)&Bf,  g_B);
    cudaGetSymbolAddress((void**)&C,   g_C);
    cudaGetSymbolAddress((void**)&bar, g_bar);

    // Phase 1a
    phase1a_kernel<<<BATCH, 256>>>(y, Wih, Whh, bih, bhh, Z);

    // Phase 1b: 2 chunks of 128 steps
    const int CHUNK = 128;
    const int MBIG  = CHUNK * BATCH;   // 16384
    for (int c = 0; c < TSTEPS / CHUNK; c++) {
        const float* Xz = Z + (size_t)c * CHUNK * ZSTRIDE;
        gemm_big<1><<<dim3(HID/128, MBIG/128), 256>>>(Xz, LAT, W1, LAT, b1, A, HID, LAT);
        gemm_big<1><<<dim3(HID/128, MBIG/128), 256>>>(A, HID, W2, HID, b2, Bf, HID, HID);
        gemm_big<1><<<dim3(HID/128, MBIG/128), 256>>>(Bf, HID, W3, HID, b3, A, HID, HID);
        gemm_big<1><<<dim3(HID/128, MBIG/128), 256>>>(A, HID, W4, HID, b4, Bf, HID, HID);
        gemm_out<<<dim3(1, MBIG/128), 256>>>(Bf, HID, W5, HID, b5, out, HID, c * CHUNK);
    }

    // Phase 2
    cudaMemsetAsync(bar, 0, sizeof(unsigned));
    phase2_kernel<<<NB2, 128>>>(W1, b1, W2, b2, W3, b3, W4, b4, W5, b5,
                                Wih, Whh, bih, bhh, Z, A, C, out);
}

// round 6
// speedup vs baseline: 1.0129x; 1.0129x over previous
#include <cuda_runtime.h>
#include <math.h>

#define BATCH   128
#define TSTEPS  256
#define HORIZON 512
#define OBS     32
#define LAT     256
#define HID     1024
#define NB2     264              // 256 layer CTAs + 8 Whh CTAs, all co-resident
#define ZSTRIDE (BATCH * LAT)

// ---------------------------------------------------------------------------
// Scratch
// ---------------------------------------------------------------------------
__device__ float g_Z[(size_t)(HORIZON + 1) * ZSTRIDE];
__device__ float g_A[(size_t)128 * BATCH * HID];   // phase1b acts / phase2 partials
__device__ float g_B[(size_t)128 * BATCH * HID];
__device__ float g_C[BATCH * LAT];
__device__ unsigned g_ctr;                 // barrier arrival counter
__device__ unsigned g_rel[NB2 * 32];       // per-CTA release words, 128B apart

// ---------------------------------------------------------------------------
// f32x2 helpers
// ---------------------------------------------------------------------------
typedef unsigned long long u64;
__device__ __forceinline__ u64 f2dup(float s) {
    u64 r; asm("mov.b64 %0, {%1, %1};" : "=l"(r) : "f"(s)); return r;
}
__device__ __forceinline__ void f2fma(u64& d, u64 a, u64 b) {
    asm("fma.rn.f32x2 %0, %1, %2, %0;" : "+l"(d) : "l"(a), "l"(b));
}
__device__ __forceinline__ float2 f2unpack(u64 v) {
    float2 r; asm("mov.b64 {%0, %1}, %2;" : "=f"(r.x), "=f"(r.y) : "l"(v)); return r;
}

// ---------------------------------------------------------------------------
// Distributed-flag grid barrier.
// Arrival: one atomicAdd per CTA (single address, cheap drain).
// Release: CTA 0 polls the counter, then writes one epoch word per CTA,
//          each on its own 128B line; every CTA polls only ITS line.
// ---------------------------------------------------------------------------
__device__ __forceinline__ void gsync(unsigned& epoch) {
    epoch++;
    __syncthreads();
    __threadfence();
    const int bid = blockIdx.x, tid = threadIdx.x;
    if (bid == 0) {
        if (tid == 0) {
            atomicAdd(&g_ctr, 1u);
            const unsigned goal = epoch * gridDim.x;
            while (*((volatile unsigned*)&g_ctr) < goal) {}
            __threadfence();
        }
        __syncthreads();
        for (int i = tid; i < (int)gridDim.x; i += blockDim.x)
            *((volatile unsigned*)&g_rel[i * 32]) = epoch;
        __syncthreads();
    } else {
        if (tid == 0) {
            atomicAdd(&g_ctr, 1u);
            volatile unsigned* my = &g_rel[bid * 32];
            while (*my < epoch) {}
            __threadfence();
        }
        __syncthreads();
    }
}

// ---------------------------------------------------------------------------
// Phase 1a: barrier-free recurrence. CTA b owns batch row b.
// ---------------------------------------------------------------------------
__global__ void __launch_bounds__(256) phase1a_kernel(
    const float* __restrict__ y,
    const float* __restrict__ Wih, const float* __restrict__ Whh,
    const float* __restrict__ bih, const float* __restrict__ bhh,
    float* __restrict__ Z)
{
    const int b = blockIdx.x, tid = threadIdx.x;
    __shared__ float sz[LAT];
    __shared__ float sy[OBS];

    sz[tid] = 0.0f;
    __stcg(Z + (size_t)b * LAT + tid, 0.0f);
    float bsum = __ldg(bih + tid) + __ldg(bhh + tid);

    float4 wi[8];
    const float4* wip = (const float4*)(Wih + (size_t)tid * OBS);
#pragma unroll
    for (int k = 0; k < 8; k++) wi[k] = __ldg(wip + k);
    const float4* wh = (const float4*)(Whh + (size_t)tid * LAT);
    __syncthreads();

    for (int t = 0; t < TSTEPS; t++) {
        if (tid < OBS) sy[tid] = __ldg(y + ((size_t)b * TSTEPS + t) * OBS + tid);
        __syncthreads();
        float acc = bsum;
#pragma unroll
        for (int k = 0; k < 8; k++) {
            float4 w = wi[k];
            acc += sy[k*4+0]*w.x + sy[k*4+1]*w.y + sy[k*4+2]*w.z + sy[k*4+3]*w.w;
        }
#pragma unroll 8
        for (int k = 0; k < 64; k++) {
            float4 w = __ldg(wh + k);
            acc += sz[k*4+0]*w.x + sz[k*4+1]*w.y + sz[k*4+2]*w.z + sz[k*4+3]*w.w;
        }
        float zn = tanhf(acc);
        __syncthreads();
        sz[tid] = zn;
        __stcg(Z + ((size_t)t + 1) * ZSTRIDE + (size_t)b * LAT + tid, zn);
    }
}

// ---------------------------------------------------------------------------
// Phase 1b GEMM: 128x128 tile, 8x8 microtile, f32x2.
// ---------------------------------------------------------------------------
template<int ACT>
__global__ void __launch_bounds__(256, 2) gemm_big(
    const float* __restrict__ X, int ldx,
    const float* __restrict__ W, int ldw,
    const float* __restrict__ bias,
    float* __restrict__ Y, int ldy, int K)
{
    __shared__ __align__(16) float sX[16 * 132];
    __shared__ __align__(16) float sW[16 * 132];
    const int tid = threadIdx.x;
    const int ty = tid >> 4, tx = tid & 15;
    const int mB = blockIdx.y * 128, nB = blockIdx.x * 128;
    const int xr = tid >> 2, xc = tid & 3;

    const float* Xp0 = X + (size_t)(mB + xr) * ldx + xc * 4;
    const float* Xp1 = Xp0 + (size_t)64 * ldx;
    const float* Wp0 = W + (size_t)(nB + xr) * ldw + xc * 4;
    const float* Wp1 = Wp0 + (size_t)64 * ldw;

    float4 xv0 = __ldg((const float4*)Xp0);
    float4 xv1 = __ldg((const float4*)Xp1);
    float4 wv0 = __ldg((const float4*)Wp0);
    float4 wv1 = __ldg((const float4*)Wp1);

    u64 acc[4][8];
#pragma unroll
    for (int i = 0; i < 4; i++)
#pragma unroll
        for (int j = 0; j < 8; j++) acc[i][j] = 0ull;

    for (int k0 = 0;;) {
        sX[(xc*4+0)*132 + xr] = xv0.x; sX[(xc*4+1)*132 + xr] = xv0.y;
        sX[(xc*4+2)*132 + xr] = xv0.z; sX[(xc*4+3)*132 + xr] = xv0.w;
        sX[(xc*4+0)*132 + xr+64] = xv1.x; sX[(xc*4+1)*132 + xr+64] = xv1.y;
        sX[(xc*4+2)*132 + xr+64] = xv1.z; sX[(xc*4+3)*132 + xr+64] = xv1.w;
        sW[(xc*4+0)*132 + xr] = wv0.x; sW[(xc*4+1)*132 + xr] = wv0.y;
        sW[(xc*4+2)*132 + xr] = wv0.z; sW[(xc*4+3)*132 + xr] = wv0.w;
        sW[(xc*4+0)*132 + xr+64] = wv1.x; sW[(xc*4+1)*132 + xr+64] = wv1.y;
        sW[(xc*4+2)*132 + xr+64] = wv1.z; sW[(xc*4+3)*132 + xr+64] = wv1.w;
        __syncthreads();

        const int k1 = k0 + 16;
        if (k1 < K) {
            xv0 = __ldg((const float4*)(Xp0 + k1));
            xv1 = __ldg((const float4*)(Xp1 + k1));
            wv0 = __ldg((const float4*)(Wp0 + k1));
            wv1 = __ldg((const float4*)(Wp1 + k1));
        }
#pragma unroll
        for (int kk = 0; kk < 16; kk++) {
            ulonglong2 aA = *(const ulonglong2*)&sX[kk*132 + ty*8];
            ulonglong2 aB = *(const ulonglong2*)&sX[kk*132 + ty*8 + 4];
            float4 b0 = *(const float4*)&sW[kk*132 + tx*8];
            float4 b1 = *(const float4*)&sW[kk*132 + tx*8 + 4];
            u64 bd[8];
            bd[0]=f2dup(b0.x); bd[1]=f2dup(b0.y); bd[2]=f2dup(b0.z); bd[3]=f2dup(b0.w);
            bd[4]=f2dup(b1.x); bd[5]=f2dup(b1.y); bd[6]=f2dup(b1.z); bd[7]=f2dup(b1.w);
#pragma unroll
            for (int j = 0; j < 8; j++) {
                f2fma(acc[0][j], aA.x, bd[j]);
                f2fma(acc[1][j], aA.y, bd[j]);
                f2fma(acc[2][j], aB.x, bd[j]);
                f2fma(acc[3][j], aB.y, bd[j]);
            }
        }
        __syncthreads();
        if (k1 >= K) break;
        k0 = k1;
    }

    float4 bb0 = __ldg((const float4*)(bias + nB + tx * 8));
    float4 bb1 = __ldg((const float4*)(bias + nB + tx * 8 + 4));
#pragma unroll
    for (int mp = 0; mp < 4; mp++) {
        float2 u[8];
#pragma unroll
        for (int j = 0; j < 8; j++) u[j] = f2unpack(acc[mp][j]);
        float4 r0a = make_float4(u[0].x+bb0.x, u[1].x+bb0.y, u[2].x+bb0.z, u[3].x+bb0.w);
        float4 r0b = make_float4(u[4].x+bb1.x, u[5].x+bb1.y, u[6].x+bb1.z, u[7].x+bb1.w);
        float4 r1a = make_float4(u[0].y+bb0.x, u[1].y+bb0.y, u[2].y+bb0.z, u[3].y+bb0.w);
        float4 r1b = make_float4(u[4].y+bb1.x, u[5].y+bb1.y, u[6].y+bb1.z, u[7].y+bb1.w);
        if (ACT) {
            r0a.x=fmaxf(r0a.x,0.f); r0a.y=fmaxf(r0a.y,0.f); r0a.z=fmaxf(r0a.z,0.f); r0a.w=fmaxf(r0a.w,0.f);
            r0b.x=fmaxf(r0b.x,0.f); r0b.y=fmaxf(r0b.y,0.f); r0b.z=fmaxf(r0b.z,0.f); r0b.w=fmaxf(r0b.w,0.f);
            r1a.x=fmaxf(r1a.x,0.f); r1a.y=fmaxf(r1a.y,0.f); r1a.z=fmaxf(r1a.z,0.f); r1a.w=fmaxf(r1a.w,0.f);
            r1b.x=fmaxf(r1b.x,0.f); r1b.y=fmaxf(r1b.y,0.f); r1b.z=fmaxf(r1b.z,0.f); r1b.w=fmaxf(r1b.w,0.f);
        }
        const int row0 = mB + ty * 8 + mp * 2;
        float* y0 = Y + (size_t)row0 * ldy + nB + tx * 8;
        float* y1 = y0 + ldy;
        *(float4*)y0 = r0a; *(float4*)(y0 + 4) = r0b;
        *(float4*)y1 = r1a; *(float4*)(y1 + 4) = r1b;
    }
}

// ---------------------------------------------------------------------------
// Phase 1b output layer.
// ---------------------------------------------------------------------------
__global__ void __launch_bounds__(256) gemm_out(
    const float* __restrict__ X, int ldx,
    const float* __restrict__ W, int ldw,
    const float* __restrict__ bias,
    float* __restrict__ out, int K, int t0)
{
    __shared__ __align__(16) float sX[16 * 132];
    __shared__ __align__(16) float sW[16 * 36];
    const int tid = threadIdx.x;
    const int ty = tid >> 4, tx = tid & 15;
    const int mB = blockIdx.y * 128;
    const int xr = tid >> 2, xc = tid & 3;

    const float* Xp0 = X + (size_t)(mB + xr) * ldx + xc * 4;
    const float* Xp1 = Xp0 + (size_t)64 * ldx;
    const bool wp = tid < 128;
    const float* Wp = W + (size_t)xr * ldw + xc * 4;

    float4 xv0 = __ldg((const float4*)Xp0);
    float4 xv1 = __ldg((const float4*)Xp1);
    float4 wv = make_float4(0,0,0,0);
    if (wp) wv = __ldg((const float4*)Wp);

    float acc[8][2];
#pragma unroll
    for (int i = 0; i < 8; i++) { acc[i][0] = 0.f; acc[i][1] = 0.f; }

    for (int k0 = 0;;) {
        sX[(xc*4+0)*132 + xr] = xv0.x; sX[(xc*4+1)*132 + xr] = xv0.y;
        sX[(xc*4+2)*132 + xr] = xv0.z; sX[(xc*4+3)*132 + xr] = xv0.w;
        sX[(xc*4+0)*132 + xr+64] = xv1.x; sX[(xc*4+1)*132 + xr+64] = xv1.y;
        sX[(xc*4+2)*132 + xr+64] = xv1.z; sX[(xc*4+3)*132 + xr+64] = xv1.w;
        if (wp) {
            sW[(xc*4+0)*36 + xr] = wv.x; sW[(xc*4+1)*36 + xr] = wv.y;
            sW[(xc*4+2)*36 + xr] = wv.z; sW[(xc*4+3)*36 + xr] = wv.w;
        }
        __syncthreads();
        const int k1 = k0 + 16;
        if (k1 < K) {
            xv0 = __ldg((const float4*)(Xp0 + k1));
            xv1 = __ldg((const float4*)(Xp1 + k1));
            if (wp) wv = __ldg((const float4*)(Wp + k1));
        }
#pragma unroll
        for (int kk = 0; kk < 16; kk++) {
            float4 a0 = *(const float4*)&sX[kk*132 + ty*8];
            float4 a1 = *(const float4*)&sX[kk*132 + ty*8 + 4];
            float2 b  = *(const float2*)&sW[kk*36 + tx*2];
            acc[0][0]+=a0.x*b.x; acc[0][1]+=a0.x*b.y;
            acc[1][0]+=a0.y*b.x; acc[1][1]+=a0.y*b.y;
            acc[2][0]+=a0.z*b.x; acc[2][1]+=a0.z*b.y;
            acc[3][0]+=a0.w*b.x; acc[3][1]+=a0.w*b.y;
            acc[4][0]+=a1.x*b.x; acc[4][1]+=a1.x*b.y;
            acc[5][0]+=a1.y*b.x; acc[5][1]+=a1.y*b.y;
            acc[6][0]+=a1.z*b.x; acc[6][1]+=a1.z*b.y;
            acc[7][0]+=a1.w*b.x; acc[7][1]+=a1.w*b.y;
        }
        __syncthreads();
        if (k1 >= K) break;
        k0 = k1;
    }

    float2 bb = *(const float2*)(bias + tx * 2);
#pragma unroll
    for (int i = 0; i < 8; i++) {
        int r = mB + ty * 8 + i;
        int b = r & (BATCH - 1);
        int t = t0 + (r >> 7);
        float2 v = make_float2(acc[i][0] + bb.x, acc[i][1] + bb.y);
        *(float2*)(out + ((size_t)b * HORIZON + t) * OBS + tx * 2) = v;
    }
}

// ---------------------------------------------------------------------------
// Phase-2 split-K tile: 16x64, 128 thr; raw partial over [kOff, kOff+Keff).
// COMBINE: X element = relu(X0 + X1 + bIn) fused at load time.
// ---------------------------------------------------------------------------
template<bool COMBINE>
__device__ __forceinline__ void tile16x64(
    int mB, int nB, int kOff, int Keff,
    const float* __restrict__ X0, const float* __restrict__ X1,
    const float* __restrict__ bIn, int ldx,
    const float* __restrict__ W, int ldw,
    float* __restrict__ Pout, int ldp,
    float* sX, float* sW)
{
    const int tid = threadIdx.x;
    const int ty = tid >> 4, tx = tid & 15;
    const int xr = tid >> 3, xc = tid & 7;

    const float* Xp = X0 + (size_t)(mB + xr) * ldx + kOff + xc * 4;
    const float* Xq = X1 + (size_t)(mB + xr) * ldx + kOff + xc * 4;
    const float* Bp = bIn + kOff + xc * 4;
    const float* Wp = W + (size_t)(nB + xr) * ldw + kOff + xc * 4;

    float4 xv;
    {
        float4 a = __ldcg((const float4*)Xp);
        if constexpr (COMBINE) {
            float4 b = __ldcg((const float4*)Xq);
            float4 c = __ldg((const float4*)Bp);
            xv = make_float4(fmaxf(a.x+b.x+c.x, 0.f), fmaxf(a.y+b.y+c.y, 0.f),
                             fmaxf(a.z+b.z+c.z, 0.f), fmaxf(a.w+b.w+c.w, 0.f));
        } else xv = a;
    }
    float4 wv[4];
#pragma unroll
    for (int j = 0; j < 4; j++)
        wv[j] = __ldg((const float4*)(Wp + (size_t)(j * 16) * ldw));

    u64 acc[2][2] = {{0ull,0ull},{0ull,0ull}};

    for (int k0 = 0;;) {
        sX[(xc*4+0)*17 + xr] = xv.x; sX[(xc*4+1)*17 + xr] = xv.y;
        sX[(xc*4+2)*17 + xr] = xv.z; sX[(xc*4+3)*17 + xr] = xv.w;
#pragma unroll
        for (int j = 0; j < 4; j++) {
            int wr = xr + j * 16;
            sW[(xc*4+0)*68 + wr] = wv[j].x; sW[(xc*4+1)*68 + wr] = wv[j].y;
            sW[(xc*4+2)*68 + wr] = wv[j].z; sW[(xc*4+3)*68 + wr] = wv[j].w;
        }
        __syncthreads();
        const int k1 = k0 + 32;
        if (k1 < Keff) {
            float4 a = __ldcg((const float4*)(Xp + k1));
            if constexpr (COMBINE) {
                float4 b = __ldcg((const float4*)(Xq + k1));
                float4 c = __ldg((const float4*)(Bp + k1));
                xv = make_float4(fmaxf(a.x+b.x+c.x, 0.f), fmaxf(a.y+b.y+c.y, 0.f),
                                 fmaxf(a.z+b.z+c.z, 0.f), fmaxf(a.w+b.w+c.w, 0.f));
            } else xv = a;
#pragma unroll
            for (int j = 0; j < 4; j++)
                wv[j] = __ldg((const float4*)(Wp + (size_t)(j * 16) * ldw + k1));
        }
#pragma unroll
        for (int kk = 0; kk < 32; kk++) {
            u64 a0 = f2dup(sX[kk*17 + ty]);
            u64 a1 = f2dup(sX[kk*17 + ty + 8]);
            ulonglong2 bp = *(const ulonglong2*)&sW[kk*68 + tx*4];
            f2fma(acc[0][0], a0, bp.x); f2fma(acc[0][1], a0, bp.y);
            f2fma(acc[1][0], a1, bp.x); f2fma(acc[1][1], a1, bp.y);
        }
        __syncthreads();
        if (k1 >= Keff) break;
        k0 = k1;
    }

#pragma unroll
    for (int i = 0; i < 2; i++) {
        int row = mB + ty + i * 8;
        float2 p0 = f2unpack(acc[i][0]);
        float2 p1 = f2unpack(acc[i][1]);
        float4 v = make_float4(p0.x, p0.y, p1.x, p1.y);
        __stcg((float4*)(Pout + (size_t)row * ldp + nB + tx * 4), v);
    }
}

// ---------------------------------------------------------------------------
// Phase 2: persistent AR rollout, 264 CTAs, 5 barriers/step.
// ---------------------------------------------------------------------------
__global__ void __launch_bounds__(128) phase2_kernel(
    const float* __restrict__ W1, const float* __restrict__ b1,
    const float* __restrict__ W2, const float* __restrict__ b2,
    const float* __restrict__ W3, const float* __restrict__ b3,
    const float* __restrict__ W4, const float* __restrict__ b4,
    const float* __restrict__ W5, const float* __restrict__ b5,
    const float* __restrict__ Wih, const float* __restrict__ Whh,
    const float* __restrict__ bih, const float* __restrict__ bhh,
    float* __restrict__ Z, float* __restrict__ P,
    float* __restrict__ C, float* __restrict__ out)
{
    __shared__ __align__(16) float sX[32 * 17];
    __shared__ __align__(16) float sW[32 * 68];
    unsigned epoch = 0;
    const int bid = blockIdx.x;
    const int tid = threadIdx.x;

    float* PA0 = P;
    float* PA1 = P + 131072;
    float* PB0 = P + 262144;
    float* PB1 = P + 393216;

    const int ksel = bid & 1;
    const int tile = bid >> 1;
    const int mT = (tile >> 4) * 16;
    const int nT = (tile & 15) * 64;

    for (int t = TSTEPS; t < HORIZON; t++) {
        const float* z = Z + (size_t)t * ZSTRIDE;

        // R1: L1 (K=256, split 128) -> PA ; Whh tiles 0..7
        if (bid < 256) {
            tile16x64<false>(mT, nT, ksel * 128, 128, z, z, b1, LAT,
                             W1, LAT, ksel ? PA1 : PA0, HID, sX, sW);
        } else {
            int wt = bid - 256;
            tile16x64<false>((wt >> 2) * 16, (wt & 3) * 64, 0, LAT, z, z, b1, LAT,
                             Whh, LAT, C, LAT, sX, sW);
        }
        gsync(epoch);

        // R2: L2 = relu(PA0+PA1+b1) @ W2 (split 512) -> PB ; Whh 8..15
        if (bid < 256) {
            tile16x64<true>(mT, nT, ksel * 512, 512, PA0, PA1, b1, HID,
                            W2, HID, ksel ? PB1 : PB0, HID, sX, sW);
        } else {
            int wt = 8 + (bid - 256);
            tile16x64<false>((wt >> 2) * 16, (wt & 3) * 64, 0, LAT, z, z, b1, LAT,
                             Whh, LAT, C, LAT, sX, sW);
        }
        gsync(epoch);

        // R3: L3 -> PA ; Whh 16..23
        if (bid < 256) {
            tile16x64<true>(mT, nT, ksel * 512, 512, PB0, PB1, b2, HID,
                            W3, HID, ksel ? PA1 : PA0, HID, sX, sW);
        } else {
            int wt = 16 + (bid - 256);
            tile16x64<false>((wt >> 2) * 16, (wt & 3) * 64, 0, LAT, z, z, b1, LAT,
                             Whh, LAT, C, LAT, sX, sW);
        }
        gsync(epoch);

        // R4: L4 -> PB ; Whh 24..31
        if (bid < 256) {
            tile16x64<true>(mT, nT, ksel * 512, 512, PA0, PA1, b3, HID,
                            W4, HID, ksel ? PB1 : PB0, HID, sX, sW);
        } else {
            int wt = 24 + (bid - 256);
            tile16x64<false>((wt >> 2) * 16, (wt & 3) * 64, 0, LAT, z, z, b1, LAT,
                             Whh, LAT, C, LAT, sX, sW);
        }
        gsync(epoch);

        // R5: CTA b: h4 = relu(PB0+PB1+b4); yh = h4 @ W5^T + b5; out; cell
        if (bid < 128) {
            const int b = bid;
            const float4* r0 = (const float4*)(PB0 + (size_t)b * HID);
            const float4* r1 = (const float4*)(PB1 + (size_t)b * HID);
            const float4* bb4 = (const float4*)b4;
            for (int i = tid; i < 256; i += 128) {
                float4 q0 = __ldcg(r0 + i);
                float4 q1 = __ldcg(r1 + i);
                float4 c4 = __ldg(bb4 + i);
                float4 v = make_float4(fmaxf(q0.x+q1.x+c4.x, 0.f),
                                       fmaxf(q0.y+q1.y+c4.y, 0.f),
                                       fmaxf(q0.z+q1.z+c4.z, 0.f),
                                       fmaxf(q0.w+q1.w+c4.w, 0.f));
                ((float4*)sW)[i] = v;
            }
            __syncthreads();
            {
                const int n = tid >> 2, q = tid & 3;
                const float4* w5 = (const float4*)(W5 + (size_t)n * HID) + q * 64;
                const float4* xb = (const float4*)sW + q * 64;
                float s = 0.f;
#pragma unroll 8
                for (int k = 0; k < 64; k++) {
                    float4 w = __ldg(w5 + k);
                    float4 x = xb[k];
                    s += x.x*w.x + x.y*w.y + x.z*w.z + x.w*w.w;
                }
                sX[tid] = s;
            }
            __syncthreads();
            if (tid < OBS) {
                float yh = sX[tid*4] + sX[tid*4+1] + sX[tid*4+2] + sX[tid*4+3]
                         + __ldg(b5 + tid);
                __stcg(out + ((size_t)b * HORIZON + t) * OBS + tid, yh);
                sX[256 + tid] = yh;
            }
            __syncthreads();
            if (t < HORIZON - 1) {
#pragma unroll
                for (int p = 0; p < 2; p++) {
                    const int n = tid + p * 128;
                    float acc = __ldcg(C + (size_t)b * LAT + n)
                              + __ldg(bih + n) + __ldg(bhh + n);
                    const float4* wr = (const float4*)(Wih + (size_t)n * OBS);
#pragma unroll
                    for (int k = 0; k < 8; k++) {
                        float4 w = __ldg(wr + k);
                        acc += sX[256+k*4+0]*w.x + sX[256+k*4+1]*w.y
                             + sX[256+k*4+2]*w.z + sX[256+k*4+3]*w.w;
                    }
                    __stcg(Z + ((size_t)t + 1) * ZSTRIDE + (size_t)b * LAT + n, tanhf(acc));
                }
            }
        }
        gsync(epoch);
    }
}

// ---------------------------------------------------------------------------
// Launch (~14 graph nodes)
// ---------------------------------------------------------------------------
extern "C" void kernel_launch(void* const* d_in, const int* in_sizes, int n_in,
                              void* d_out, int out_size)
{
    const float* y   = (const float*)d_in[0];
    const float* Wih = (const float*)d_in[2];
    const float* Whh = (const float*)d_in[3];
    const float* bih = (const float*)d_in[4];
    const float* bhh = (const float*)d_in[5];
    const float* W1  = (const float*)d_in[6];
    const float* b1  = (const float*)d_in[7];
    const float* W2  = (const float*)d_in[8];
    const float* b2  = (const float*)d_in[9];
    const float* W3  = (const float*)d_in[10];
    const float* b3  = (const float*)d_in[11];
    const float* W4  = (const float*)d_in[12];
    const float* b4  = (const float*)d_in[13];
    const float* W5  = (const float*)d_in[14];
    const float* b5  = (const float*)d_in[15];
    float* out = (float*)d_out;

    float *Z, *A, *Bf, *C;
    unsigned *ctr, *rel;
    cudaGetSymbolAddress((void**)&Z,   g_Z);
    cudaGetSymbolAddress((void**)&A,   g_A);
    cudaGetSymbolAddress((void**)&Bf,  g_B);
    cudaGetSymbolAddress((void**)&C,   g_C);
    cudaGetSymbolAddress((void**)&ctr, g_ctr);
    cudaGetSymbolAddress((void**)&rel, g_rel);

    // Phase 1a
    phase1a_kernel<<<BATCH, 256>>>(y, Wih, Whh, bih, bhh, Z);

    // Phase 1b: 2 chunks of 128 steps
    const int CHUNK = 128;
    const int MBIG  = CHUNK * BATCH;
    for (int c = 0; c < TSTEPS / CHUNK; c++) {
        const float* Xz = Z + (size_t)c * CHUNK * ZSTRIDE;
        gemm_big<1><<<dim3(HID/128, MBIG/128), 256>>>(Xz, LAT, W1, LAT, b1, A, HID, LAT);
        gemm_big<1><<<dim3(HID/128, MBIG/128), 256>>>(A, HID, W2, HID, b2, Bf, HID, HID);
        gemm_big<1><<<dim3(HID/128, MBIG/128), 256>>>(Bf, HID, W3, HID, b3, A, HID, HID);
        gemm_big<1><<<dim3(HID/128, MBIG/128), 256>>>(A, HID, W4, HID, b4, Bf, HID, HID);
        gemm_out<<<dim3(1, MBIG/128), 256>>>(Bf, HID, W5, HID, b5, out, HID, c * CHUNK);
    }

    // Phase 2: reset barrier state, then persistent rollout
    cudaMemsetAsync(ctr, 0, sizeof(unsigned));
    cudaMemsetAsync(rel, 0, sizeof(unsigned) * NB2 * 32);
    phase2_kernel<<<NB2, 128>>>(W1, b1, W2, b2, W3, b3, W4, b4, W5, b5,
                                Wih, Whh, bih, bhh, Z, A, C, out);
}